// round 3
// baseline (speedup 1.0000x reference)
#include <cuda_runtime.h>

// ---------------- problem constants (max sizes for static scratch) ----------
#define NN   50000
#define EE   800000
#define KDIM 128
#define CMAX 640     // (R+1)*128

// ---------------- device scratch (no allocations allowed) -------------------
static __device__ float g_hcat[(size_t)NN * CMAX];  // GEMM output: [root | W0..W3] blocks
static __device__ float g_bufA[(size_t)NN * 128];   // layer activations (ping)
static __device__ float g_bufB[(size_t)NN * 128];   // layer activations (pong)
static __device__ float g_wcat[KDIM * CMAX];        // concatenated weights for current layer
static __device__ float g_q[16 * 64];               // relu(question @ qn_W + qn_b)
static __device__ int   g_cnt4[NN * 4];             // per-(node,relation) in-degree
static __device__ float g_icnt[NN * 4];             // 1/max(cnt,1)
static __device__ int   g_deg[NN];                  // total in-degree
static __device__ int   g_offs[NN + 1];             // CSR row offsets (by dst)
static __device__ int   g_cursor[NN];               // fill cursors
static __device__ int   g_csr[EE];                  // packed (src<<2)|etype, grouped by dst

// ---------------- small kernels ---------------------------------------------

// q = relu(question_embedding @ qn_W + qn_b)   [16 x 64], K = 768
__global__ void q_kernel(const float* __restrict__ qe,
                         const float* __restrict__ W,
                         const float* __restrict__ b) {
    int g = blockIdx.x;      // 0..15
    int j = threadIdx.x;     // 0..63
    const float* qr = qe + (size_t)g * 768;
    float s = b[j];
    #pragma unroll 4
    for (int k = 0; k < 768; k++)
        s = fmaf(qr[k], W[(size_t)k * 64 + j], s);
    g_q[g * 64 + j] = fmaxf(s, 0.f);
}

__global__ void zero_cnt_kernel(int n4) {
    int i = blockIdx.x * 256 + threadIdx.x;
    if (i < n4) g_cnt4[i] = 0;
}

__global__ void count_kernel(const int* __restrict__ dst,
                             const int* __restrict__ et, int E) {
    int e = blockIdx.x * 256 + threadIdx.x;
    if (e < E) atomicAdd(&g_cnt4[dst[e] * 4 + et[e]], 1);
}

__global__ void prep_kernel(int n) {
    int i = blockIdx.x * 256 + threadIdx.x;
    if (i < n) {
        int d = 0;
        #pragma unroll
        for (int r = 0; r < 4; r++) {
            int c = g_cnt4[i * 4 + r];
            d += c;
            g_icnt[i * 4 + r] = 1.f / (float)(c > 0 ? c : 1);
        }
        g_deg[i] = d;
    }
}

// single-block exclusive scan over g_deg -> g_offs (and copies into g_cursor)
__global__ void scan_kernel(int n) {
    __shared__ int s[1024];
    __shared__ int carry_s;
    int t = threadIdx.x;
    if (t == 0) carry_s = 0;
    __syncthreads();
    for (int base = 0; base < n; base += 1024) {
        int v = (base + t < n) ? g_deg[base + t] : 0;
        s[t] = v;
        __syncthreads();
        for (int off = 1; off < 1024; off <<= 1) {
            int x = (t >= off) ? s[t - off] : 0;
            __syncthreads();
            s[t] += x;
            __syncthreads();
        }
        int incl = s[t];
        int ex = carry_s + incl - v;
        if (base + t < n) { g_offs[base + t] = ex; g_cursor[base + t] = ex; }
        __syncthreads();
        if (t == 1023) carry_s += s[1023];
        __syncthreads();
    }
    if (t == 0) g_offs[n] = carry_s;
}

__global__ void fill_kernel(const int* __restrict__ src,
                            const int* __restrict__ dst,
                            const int* __restrict__ et, int E) {
    int e = blockIdx.x * 256 + threadIdx.x;
    if (e < E) {
        int d = dst[e];
        int pos = atomicAdd(&g_cursor[d], 1);
        g_csr[pos] = (src[e] << 2) | et[e];
    }
}

// build [root | W0 | W1 | W2 | W3] -> g_wcat [K=128, C=(R+1)*OUT]
__global__ void wcat_kernel(const float* __restrict__ root,
                            const float* __restrict__ W, int OUT, int C) {
    int idx = blockIdx.x * 256 + threadIdx.x;
    if (idx < 128 * C) {
        int k = idx / C, c = idx % C;
        float v;
        if (c < OUT) v = root[k * OUT + c];
        else {
            int r = c / OUT - 1;
            int o = c - (r + 1) * OUT;
            v = W[((size_t)r * 128 + k) * OUT + o];
        }
        g_wcat[idx] = v;
    }
}

// comb[:, 64:128] = q[batch[i]]
__global__ void qfill_kernel(const int* __restrict__ batch, int n) {
    int t = blockIdx.x * 256 + threadIdx.x;
    if (t < n * 64) {
        int i = t >> 6, j = t & 63;
        g_bufA[(size_t)i * 128 + 64 + j] = g_q[batch[i] * 64 + j];
    }
}

// ---------------- GEMM: g_hcat[M,C] = A[M,128] @ g_wcat[128,C] --------------
// BM=128, BN=64, BK=16, 256 threads, TM=8, TN=4
__global__ void __launch_bounds__(256) gemm_kernel(const float* __restrict__ A,
                                                   int M, int C) {
    __shared__ float As[16][128];
    __shared__ float Bs[16][68];
    int tid = threadIdx.x;
    int tx = tid & 15;        // 0..15 (cols, TN=4)
    int ty = tid >> 4;        // 0..15 (rows, TM=8)
    int row0 = blockIdx.y * 128;
    int col0 = blockIdx.x * 64;
    int a_m  = tid & 127;
    int a_kg = tid >> 7;      // 0/1 -> covers k offsets 0..7 / 8..15
    int b_k  = tid >> 4;      // 0..15
    int b_c  = (tid & 15) * 4;

    float acc[8][4];
    #pragma unroll
    for (int i = 0; i < 8; i++)
        #pragma unroll
        for (int j = 0; j < 4; j++) acc[i][j] = 0.f;

    const float* Arow = A + (size_t)(row0 + a_m) * 128;
    bool avalid = (row0 + a_m) < M;

    for (int k0 = 0; k0 < 128; k0 += 16) {
        float4 av0 = make_float4(0.f, 0.f, 0.f, 0.f);
        float4 av1 = av0;
        if (avalid) {
            av0 = *(const float4*)(Arow + k0 + a_kg * 8);
            av1 = *(const float4*)(Arow + k0 + a_kg * 8 + 4);
        }
        float4 bv = *(const float4*)(g_wcat + (size_t)(k0 + b_k) * C + col0 + b_c);
        __syncthreads();
        int kk = a_kg * 8;
        As[kk + 0][a_m] = av0.x; As[kk + 1][a_m] = av0.y;
        As[kk + 2][a_m] = av0.z; As[kk + 3][a_m] = av0.w;
        As[kk + 4][a_m] = av1.x; As[kk + 5][a_m] = av1.y;
        As[kk + 6][a_m] = av1.z; As[kk + 7][a_m] = av1.w;
        *(float4*)&Bs[b_k][b_c] = bv;
        __syncthreads();
        #pragma unroll
        for (int k = 0; k < 16; k++) {
            float4 b4 = *(const float4*)&Bs[k][tx * 4];
            float4 a0 = *(const float4*)&As[k][ty * 8];
            float4 a1 = *(const float4*)&As[k][ty * 8 + 4];
            float ar[8] = {a0.x, a0.y, a0.z, a0.w, a1.x, a1.y, a1.z, a1.w};
            float br[4] = {b4.x, b4.y, b4.z, b4.w};
            #pragma unroll
            for (int i = 0; i < 8; i++)
                #pragma unroll
                for (int j = 0; j < 4; j++)
                    acc[i][j] = fmaf(ar[i], br[j], acc[i][j]);
        }
    }
    #pragma unroll
    for (int i = 0; i < 8; i++) {
        int r = row0 + ty * 8 + i;
        if (r < M)
            *(float4*)(g_hcat + (size_t)r * C + col0 + tx * 4) =
                make_float4(acc[i][0], acc[i][1], acc[i][2], acc[i][3]);
    }
}

// ---------------- aggregation: warp per node, CSR gather, no atomics --------
template <int OUT>
__global__ void __launch_bounds__(256) agg_kernel(const float* __restrict__ bias,
                                                  float* __restrict__ out,
                                                  int ldo, int M, int C, int relu) {
    int w = (blockIdx.x * 256 + threadIdx.x) >> 5;
    int lane = threadIdx.x & 31;
    if (w >= M) return;
    constexpr int V = OUT / 32;
    float acc[V];
    {
        const float* hr = g_hcat + (size_t)w * C + lane * V;   // root block
        const float* br = bias + lane * V;
        if (V == 4) {
            float4 h4 = *(const float4*)hr;
            acc[0] = h4.x + br[0]; acc[1] = h4.y + br[1];
            acc[2] = h4.z + br[2]; acc[3] = h4.w + br[3];
        } else {
            float2 h2 = *(const float2*)hr;
            acc[0] = h2.x + br[0]; acc[1] = h2.y + br[1];
        }
    }
    int beg = g_offs[w], end = g_offs[w + 1];
    const float* icn = g_icnt + w * 4;
    for (int e = beg; e < end; e++) {
        int p = g_csr[e];
        int s = p >> 2;
        int r = p & 3;
        float sc = icn[r];
        const float* m = g_hcat + (size_t)s * C + (1 + r) * OUT + lane * V;
        if (V == 4) {
            float4 mv = *(const float4*)m;
            acc[0] = fmaf(mv.x, sc, acc[0]);
            acc[1] = fmaf(mv.y, sc, acc[1]);
            acc[2] = fmaf(mv.z, sc, acc[2]);
            acc[3] = fmaf(mv.w, sc, acc[3]);
        } else {
            float2 mv = *(const float2*)m;
            acc[0] = fmaf(mv.x, sc, acc[0]);
            acc[1] = fmaf(mv.y, sc, acc[1]);
        }
    }
    float* o = out + (size_t)w * ldo + lane * V;
    if (V == 4) {
        float4 v;
        v.x = relu ? fmaxf(acc[0], 0.f) : acc[0];
        v.y = relu ? fmaxf(acc[1], 0.f) : acc[1];
        v.z = relu ? fmaxf(acc[2], 0.f) : acc[2];
        v.w = relu ? fmaxf(acc[3], 0.f) : acc[3];
        *(float4*)o = v;
    } else {
        float2 v;
        v.x = relu ? fmaxf(acc[0], 0.f) : acc[0];
        v.y = relu ? fmaxf(acc[1], 0.f) : acc[1];
        *(float2*)o = v;
    }
}

// ---------------- host driver ------------------------------------------------
extern "C" void kernel_launch(void* const* d_in, const int* in_sizes, int n_in,
                              void* d_out, int out_size) {
    const float* x     = (const float*)d_in[0];
    const int*   ei    = (const int*)d_in[1];
    const int*   ea    = (const int*)d_in[2];
    const int*   batch = (const int*)d_in[3];
    const float* qe    = (const float*)d_in[4];
    const float* qnW   = (const float*)d_in[5];
    const float* qnb   = (const float*)d_in[6];
    const float* W0    = (const float*)d_in[7];
    const float* root0 = (const float*)d_in[8];
    const float* b0    = (const float*)d_in[9];
    const float* W1    = (const float*)d_in[10];
    const float* root1 = (const float*)d_in[11];
    const float* b1    = (const float*)d_in[12];
    const float* W2    = (const float*)d_in[13];
    const float* root2 = (const float*)d_in[14];
    const float* b2    = (const float*)d_in[15];
    const float* W3    = (const float*)d_in[16];
    const float* root3 = (const float*)d_in[17];
    const float* b3    = (const float*)d_in[18];

    int N = in_sizes[0] / 128;
    int E = in_sizes[2];
    const int* src = ei;
    const int* dst = ei + E;

    float *bufA = nullptr, *bufB = nullptr;
    cudaGetSymbolAddress((void**)&bufA, g_bufA);
    cudaGetSymbolAddress((void**)&bufB, g_bufB);

    // --- structure precompute ---
    q_kernel<<<16, 64>>>(qe, qnW, qnb);
    zero_cnt_kernel<<<(N * 4 + 255) / 256, 256>>>(N * 4);
    count_kernel<<<(E + 255) / 256, 256>>>(dst, ea, E);
    prep_kernel<<<(N + 255) / 256, 256>>>(N);
    scan_kernel<<<1, 1024>>>(N);
    fill_kernel<<<(E + 255) / 256, 256>>>(src, dst, ea, E);

    int gemm_blocks_y = (N + 127) / 128;
    int agg_blocks = (N + 7) / 8;

    // --- layer 0: 128 -> 64, then concat with q[batch] into bufA[:,0:128] ---
    wcat_kernel<<<(128 * 320 + 255) / 256, 256>>>(root0, W0, 64, 320);
    gemm_kernel<<<dim3(5, gemm_blocks_y), 256>>>(x, N, 320);
    agg_kernel<64><<<agg_blocks, 256>>>(b0, bufA, 128, N, 320, 1);
    qfill_kernel<<<(N * 64 + 255) / 256, 256>>>(batch, N);

    // --- layer 1: 128 -> 128 ---
    wcat_kernel<<<(128 * 640 + 255) / 256, 256>>>(root1, W1, 128, 640);
    gemm_kernel<<<dim3(10, gemm_blocks_y), 256>>>(bufA, N, 640);
    agg_kernel<128><<<agg_blocks, 256>>>(b1, bufB, 128, N, 640, 1);

    // --- layer 2: 128 -> 128 ---
    wcat_kernel<<<(128 * 640 + 255) / 256, 256>>>(root2, W2, 128, 640);
    gemm_kernel<<<dim3(10, gemm_blocks_y), 256>>>(bufB, N, 640);
    agg_kernel<128><<<agg_blocks, 256>>>(b2, bufA, 128, N, 640, 1);

    // --- layer 3: 128 -> 64, no relu, write d_out ---
    wcat_kernel<<<(128 * 320 + 255) / 256, 256>>>(root3, W3, 64, 320);
    gemm_kernel<<<dim3(5, gemm_blocks_y), 256>>>(bufA, N, 320);
    agg_kernel<64><<<agg_blocks, 256>>>(b3, (float*)d_out, 64, N, 320, 0);
}

// round 7
// speedup vs baseline: 1.5593x; 1.5593x over previous
#include <cuda_runtime.h>

// ---------------- problem constants (max sizes for static scratch) ----------
#define NN   50000
#define EE   800000
#define KDIM 128
#define CMAX 640     // (R+1)*128

// ---------------- device scratch (no allocations allowed) -------------------
static __device__ float g_hcat[(size_t)NN * CMAX];  // GEMM output: [root | W0..W3] blocks
static __device__ float g_bufA[(size_t)NN * 128];   // layer activations (ping)
static __device__ float g_bufB[(size_t)NN * 128];   // layer activations (pong)
static __device__ float g_wcat[KDIM * CMAX];        // concatenated weights for current layer
static __device__ float g_q[16 * 64];               // relu(question @ qn_W + qn_b)
static __device__ int   g_cnt4[NN * 4];             // per-(node,relation) in-degree
static __device__ float g_icnt[NN * 4];             // 1/max(cnt,1)
static __device__ int   g_deg[NN];                  // total in-degree
static __device__ int   g_offs[NN + 1];             // CSR row offsets (by dst)
static __device__ int   g_cursor[NN];               // fill cursors
static __device__ int   g_csr[EE];                  // packed (src<<2)|etype, grouped by dst

// ---------------- small kernels ---------------------------------------------

// q = relu(question_embedding @ qn_W + qn_b)   [16 x 64], K = 768
__global__ void q_kernel(const float* __restrict__ qe,
                         const float* __restrict__ W,
                         const float* __restrict__ b) {
    int g = blockIdx.x;      // 0..15
    int j = threadIdx.x;     // 0..63
    const float* qr = qe + (size_t)g * 768;
    float s = b[j];
    #pragma unroll 4
    for (int k = 0; k < 768; k++)
        s = fmaf(qr[k], W[(size_t)k * 64 + j], s);
    g_q[g * 64 + j] = fmaxf(s, 0.f);
}

__global__ void zero_cnt_kernel(int n4) {
    int i = blockIdx.x * 256 + threadIdx.x;
    if (i < n4) g_cnt4[i] = 0;
}

__global__ void count_kernel(const int* __restrict__ dst,
                             const int* __restrict__ et, int E) {
    int e = blockIdx.x * 256 + threadIdx.x;
    if (e < E) atomicAdd(&g_cnt4[dst[e] * 4 + et[e]], 1);
}

__global__ void prep_kernel(int n) {
    int i = blockIdx.x * 256 + threadIdx.x;
    if (i < n) {
        int d = 0;
        #pragma unroll
        for (int r = 0; r < 4; r++) {
            int c = g_cnt4[i * 4 + r];
            d += c;
            g_icnt[i * 4 + r] = 1.f / (float)(c > 0 ? c : 1);
        }
        g_deg[i] = d;
    }
}

// single-block exclusive scan over g_deg -> g_offs (and copies into g_cursor)
__global__ void scan_kernel(int n) {
    __shared__ int s[1024];
    __shared__ int carry_s;
    int t = threadIdx.x;
    if (t == 0) carry_s = 0;
    __syncthreads();
    for (int base = 0; base < n; base += 1024) {
        int v = (base + t < n) ? g_deg[base + t] : 0;
        s[t] = v;
        __syncthreads();
        for (int off = 1; off < 1024; off <<= 1) {
            int x = (t >= off) ? s[t - off] : 0;
            __syncthreads();
            s[t] += x;
            __syncthreads();
        }
        int incl = s[t];
        int ex = carry_s + incl - v;
        if (base + t < n) { g_offs[base + t] = ex; g_cursor[base + t] = ex; }
        __syncthreads();
        if (t == 1023) carry_s += s[1023];
        __syncthreads();
    }
    if (t == 0) g_offs[n] = carry_s;
}

__global__ void fill_kernel(const int* __restrict__ src,
                            const int* __restrict__ dst,
                            const int* __restrict__ et, int E) {
    int e = blockIdx.x * 256 + threadIdx.x;
    if (e < E) {
        int d = dst[e];
        int pos = atomicAdd(&g_cursor[d], 1);
        g_csr[pos] = (src[e] << 2) | et[e];
    }
}

// build [root | W0 | W1 | W2 | W3] -> g_wcat [K=128, C=(R+1)*OUT]
__global__ void wcat_kernel(const float* __restrict__ root,
                            const float* __restrict__ W, int OUT, int C) {
    int idx = blockIdx.x * 256 + threadIdx.x;
    if (idx < 128 * C) {
        int k = idx / C, c = idx % C;
        float v;
        if (c < OUT) v = root[k * OUT + c];
        else {
            int r = c / OUT - 1;
            int o = c - (r + 1) * OUT;
            v = W[((size_t)r * 128 + k) * OUT + o];
        }
        g_wcat[idx] = v;
    }
}

// comb[:, 64:128] = q[batch[i]]
__global__ void qfill_kernel(const int* __restrict__ batch, int n) {
    int t = blockIdx.x * 256 + threadIdx.x;
    if (t < n * 64) {
        int i = t >> 6, j = t & 63;
        g_bufA[(size_t)i * 128 + 64 + j] = g_q[batch[i] * 64 + j];
    }
}

// ---------------- TF32 tensor-core GEMM -------------------------------------
// g_hcat[M,C] = A[M,128] @ g_wcat[128,C]
// block tile 128x64, 8 warps (4x2), warp tile 32x32, mma m16n8k8 tf32

__device__ __forceinline__ unsigned f2tf(float f) {
    unsigned u;
    asm("cvt.rna.tf32.f32 %0, %1;" : "=r"(u) : "f"(f));
    return u;
}

__device__ __forceinline__ void mma_tf32(float* c, const unsigned* a, const unsigned* b) {
    asm volatile("mma.sync.aligned.m16n8k8.row.col.f32.tf32.tf32.f32 "
                 "{%0,%1,%2,%3}, {%4,%5,%6,%7}, {%8,%9}, {%0,%1,%2,%3};"
                 : "+f"(c[0]), "+f"(c[1]), "+f"(c[2]), "+f"(c[3])
                 : "r"(a[0]), "r"(a[1]), "r"(a[2]), "r"(a[3]),
                   "r"(b[0]), "r"(b[1]));
}

__global__ void __launch_bounds__(256) gemm_tc_kernel(const float* __restrict__ A,
                                                      int M, int C) {
    __shared__ unsigned As[128][36];   // [m][k], ld 36 -> conflict-free frag loads
    __shared__ unsigned Bs[32][72];    // [k][n], ld 72 -> conflict-free frag loads
    int tid = threadIdx.x;
    int warp = tid >> 5, lane = tid & 31;
    int wm = warp >> 1, wn = warp & 1;
    int lg = lane >> 2;   // 0..7  (groupID)
    int lq = lane & 3;    // 0..3  (threadID_in_group)
    int row0 = blockIdx.y * 128, col0 = blockIdx.x * 64;

    float acc[2][4][4];
    #pragma unroll
    for (int t = 0; t < 2; t++)
        #pragma unroll
        for (int j = 0; j < 4; j++)
            #pragma unroll
            for (int v = 0; v < 4; v++) acc[t][j][v] = 0.f;

    int ar = tid >> 3;            // 0..31: A row within 32-row pass
    int ak = (tid & 7) * 4;       // k quad within 32-wide chunk
    int bk = tid >> 4;            // 0..15: B k within 16-row pass
    int bn = (tid & 15) * 4;      // n quad

    for (int k0 = 0; k0 < 128; k0 += 32) {
        float4 av[4], bv[2];
        #pragma unroll
        for (int p = 0; p < 4; p++) {
            int r = row0 + p * 32 + ar;
            av[p] = (r < M) ? *(const float4*)(A + (size_t)r * 128 + k0 + ak)
                            : make_float4(0.f, 0.f, 0.f, 0.f);
        }
        #pragma unroll
        for (int p = 0; p < 2; p++) {
            int k = k0 + p * 16 + bk;
            bv[p] = *(const float4*)(g_wcat + (size_t)k * C + col0 + bn);
        }
        __syncthreads();
        #pragma unroll
        for (int p = 0; p < 4; p++) {
            unsigned* d = &As[p * 32 + ar][ak];
            d[0] = f2tf(av[p].x); d[1] = f2tf(av[p].y);
            d[2] = f2tf(av[p].z); d[3] = f2tf(av[p].w);
        }
        #pragma unroll
        for (int p = 0; p < 2; p++) {
            unsigned* d = &Bs[p * 16 + bk][bn];
            d[0] = f2tf(bv[p].x); d[1] = f2tf(bv[p].y);
            d[2] = f2tf(bv[p].z); d[3] = f2tf(bv[p].w);
        }
        __syncthreads();
        #pragma unroll
        for (int ks = 0; ks < 4; ks++) {
            int kk = ks * 8;
            unsigned a[2][4], b[4][2];
            #pragma unroll
            for (int t = 0; t < 2; t++) {
                int mb = wm * 32 + t * 16;
                // PTX m16n8k8.tf32 A fragment order:
                // a0=(g, q)  a1=(g+8, q)  a2=(g, q+4)  a3=(g+8, q+4)
                a[t][0] = As[mb + lg][kk + lq];
                a[t][1] = As[mb + lg + 8][kk + lq];
                a[t][2] = As[mb + lg][kk + lq + 4];
                a[t][3] = As[mb + lg + 8][kk + lq + 4];
            }
            #pragma unroll
            for (int j = 0; j < 4; j++) {
                int nb = wn * 32 + j * 8;
                // b0=(k q, n g)  b1=(k q+4, n g)
                b[j][0] = Bs[kk + lq][nb + lg];
                b[j][1] = Bs[kk + lq + 4][nb + lg];
            }
            #pragma unroll
            for (int t = 0; t < 2; t++)
                #pragma unroll
                for (int j = 0; j < 4; j++)
                    mma_tf32(acc[t][j], a[t], b[j]);
        }
    }

    #pragma unroll
    for (int t = 0; t < 2; t++) {
        int r0 = row0 + wm * 32 + t * 16 + lg;
        #pragma unroll
        for (int j = 0; j < 4; j++) {
            int cb = col0 + wn * 32 + j * 8 + lq * 2;
            if (r0 < M)
                *(float2*)(g_hcat + (size_t)r0 * C + cb) =
                    make_float2(acc[t][j][0], acc[t][j][1]);
            if (r0 + 8 < M)
                *(float2*)(g_hcat + (size_t)(r0 + 8) * C + cb) =
                    make_float2(acc[t][j][2], acc[t][j][3]);
        }
    }
}

// ---------------- aggregation: warp per node, CSR gather, no atomics --------
template <int OUT>
__global__ void __launch_bounds__(256) agg_kernel(const float* __restrict__ bias,
                                                  float* __restrict__ out,
                                                  int ldo, int M, int C, int relu) {
    int w = (blockIdx.x * 256 + threadIdx.x) >> 5;
    int lane = threadIdx.x & 31;
    if (w >= M) return;
    constexpr int V = OUT / 32;
    float acc[V];
    {
        const float* hr = g_hcat + (size_t)w * C + lane * V;   // root block
        const float* br = bias + lane * V;
        if (V == 4) {
            float4 h4 = *(const float4*)hr;
            acc[0] = h4.x + br[0]; acc[1] = h4.y + br[1];
            acc[2] = h4.z + br[2]; acc[3] = h4.w + br[3];
        } else {
            float2 h2 = *(const float2*)hr;
            acc[0] = h2.x + br[0]; acc[1] = h2.y + br[1];
        }
    }
    int beg = g_offs[w], end = g_offs[w + 1];
    const float* icn = g_icnt + w * 4;
    for (int e = beg; e < end; e++) {
        int p = g_csr[e];
        int s = p >> 2;
        int r = p & 3;
        float sc = icn[r];
        const float* m = g_hcat + (size_t)s * C + (1 + r) * OUT + lane * V;
        if (V == 4) {
            float4 mv = *(const float4*)m;
            acc[0] = fmaf(mv.x, sc, acc[0]);
            acc[1] = fmaf(mv.y, sc, acc[1]);
            acc[2] = fmaf(mv.z, sc, acc[2]);
            acc[3] = fmaf(mv.w, sc, acc[3]);
        } else {
            float2 mv = *(const float2*)m;
            acc[0] = fmaf(mv.x, sc, acc[0]);
            acc[1] = fmaf(mv.y, sc, acc[1]);
        }
    }
    float* o = out + (size_t)w * ldo + lane * V;
    if (V == 4) {
        float4 v;
        v.x = relu ? fmaxf(acc[0], 0.f) : acc[0];
        v.y = relu ? fmaxf(acc[1], 0.f) : acc[1];
        v.z = relu ? fmaxf(acc[2], 0.f) : acc[2];
        v.w = relu ? fmaxf(acc[3], 0.f) : acc[3];
        *(float4*)o = v;
    } else {
        float2 v;
        v.x = relu ? fmaxf(acc[0], 0.f) : acc[0];
        v.y = relu ? fmaxf(acc[1], 0.f) : acc[1];
        *(float2*)o = v;
    }
}

// ---------------- host driver ------------------------------------------------
extern "C" void kernel_launch(void* const* d_in, const int* in_sizes, int n_in,
                              void* d_out, int out_size) {
    const float* x     = (const float*)d_in[0];
    const int*   ei    = (const int*)d_in[1];
    const int*   ea    = (const int*)d_in[2];
    const int*   batch = (const int*)d_in[3];
    const float* qe    = (const float*)d_in[4];
    const float* qnW   = (const float*)d_in[5];
    const float* qnb   = (const float*)d_in[6];
    const float* W0    = (const float*)d_in[7];
    const float* root0 = (const float*)d_in[8];
    const float* b0    = (const float*)d_in[9];
    const float* W1    = (const float*)d_in[10];
    const float* root1 = (const float*)d_in[11];
    const float* b1    = (const float*)d_in[12];
    const float* W2    = (const float*)d_in[13];
    const float* root2 = (const float*)d_in[14];
    const float* b2    = (const float*)d_in[15];
    const float* W3    = (const float*)d_in[16];
    const float* root3 = (const float*)d_in[17];
    const float* b3    = (const float*)d_in[18];

    int N = in_sizes[0] / 128;
    int E = in_sizes[2];
    const int* src = ei;
    const int* dst = ei + E;

    float *bufA = nullptr, *bufB = nullptr;
    cudaGetSymbolAddress((void**)&bufA, g_bufA);
    cudaGetSymbolAddress((void**)&bufB, g_bufB);

    // --- structure precompute ---
    q_kernel<<<16, 64>>>(qe, qnW, qnb);
    zero_cnt_kernel<<<(N * 4 + 255) / 256, 256>>>(N * 4);
    count_kernel<<<(E + 255) / 256, 256>>>(dst, ea, E);
    prep_kernel<<<(N + 255) / 256, 256>>>(N);
    scan_kernel<<<1, 1024>>>(N);
    fill_kernel<<<(E + 255) / 256, 256>>>(src, dst, ea, E);

    int gemm_blocks_y = (N + 127) / 128;
    int agg_blocks = (N + 7) / 8;

    // --- layer 0: 128 -> 64, then concat with q[batch] into bufA[:,0:128] ---
    wcat_kernel<<<(128 * 320 + 255) / 256, 256>>>(root0, W0, 64, 320);
    gemm_tc_kernel<<<dim3(5, gemm_blocks_y), 256>>>(x, N, 320);
    agg_kernel<64><<<agg_blocks, 256>>>(b0, bufA, 128, N, 320, 1);
    qfill_kernel<<<(N * 64 + 255) / 256, 256>>>(batch, N);

    // --- layer 1: 128 -> 128 ---
    wcat_kernel<<<(128 * 640 + 255) / 256, 256>>>(root1, W1, 128, 640);
    gemm_tc_kernel<<<dim3(10, gemm_blocks_y), 256>>>(bufA, N, 640);
    agg_kernel<128><<<agg_blocks, 256>>>(b1, bufB, 128, N, 640, 1);

    // --- layer 2: 128 -> 128 ---
    wcat_kernel<<<(128 * 640 + 255) / 256, 256>>>(root2, W2, 128, 640);
    gemm_tc_kernel<<<dim3(10, gemm_blocks_y), 256>>>(bufB, N, 640);
    agg_kernel<128><<<agg_blocks, 256>>>(b2, bufA, 128, N, 640, 1);

    // --- layer 3: 128 -> 64, no relu, write d_out ---
    wcat_kernel<<<(128 * 320 + 255) / 256, 256>>>(root3, W3, 64, 320);
    gemm_tc_kernel<<<dim3(5, gemm_blocks_y), 256>>>(bufA, N, 320);
    agg_kernel<64><<<agg_blocks, 256>>>(b3, (float*)d_out, 64, N, 320, 0);
}